// round 14
// baseline (speedup 1.0000x reference)
#include <cuda_runtime.h>

// RoPE: X (L=2048, D=4096, N=4) fp32 -> out same shape.
// ang[l,d] = fl32((l+1) * theta_d), theta_d = 10000^(d/2048), angles to ~2e7.
//
// FINAL configuration (= R6). Four measurements of this exact binary:
// 43.78 / 45.82 / 44.67 / 43.74 us -> ±~1us session noise around the
// compulsory mixed-R/W HBM floor (268 MB @ ~6.0 TB/s in-kernel, kernel
// ~36us byte-stable across captures, + ~8us fixed harness overhead).
// Search history (all bisected with measured deltas):
//   fp64 hot path -> fp32 + constexpr table   (82 -> 48.7us)
//   batched MLP (loads before compute)        (DRAM 67.7 -> 73.5%)
//   occupancy 2 -> 4 CTAs/SM (LPER=4)         (-> 43.8us; occ 5 flat)
//   persistent / span / write-through forms   all regressed (reverted)

constexpr int L    = 2048;
constexpr int D    = 4096;   // feature dim in float4 units over N=4
constexpr int HALF = 2048;
constexpr int LPER = 4;
constexpr int TPB  = 256;

// ---------------- compile-time table generation ----------------

struct alignas(16) Entry { float theta, t_hi, t_lo; int m4; };
struct Table { Entry e[HALF]; };

// exp2(x), x in [0, 13.3), rel err ~5e-16 (compile-time IEEE doubles).
constexpr double cexp2(double x)
{
    const int    n = (int)(x + 0.5);
    const double f = x - (double)n;                  // [-0.5, 0.5], exact
    const double w = f * 0.69314718055994530942;     // f * ln2, |w| <= 0.347
    double p = 1.0;
    for (int k = 16; k >= 1; --k)                    // exp(w) Taylor, Horner
        p = 1.0 + p * w / (double)k;
    double s = 1.0;
    for (int i = 0; i < n; ++i) s *= 2.0;            // exact 2^n
    return s * p;                                    // exact scaling
}

constexpr Table make_table()
{
    Table T{};
    const double LOG2C   = 13.2877123795494493915;       // log2(10000)
    const double INVPIO2 = 0.63661977236758134308;       // 2/pi
    const double PIO2    = 1.57079632679489661923;       // double(pi/2)
    const double PIO2LO  = 6.12323399573676603587e-17;   // pi/2 - PIO2
    // Dekker split of PIO2: hi has <=26 bits -> m*hi exact for m < 2^24
    const double C   = 134217729.0 * PIO2;               // 2^27+1 splitter
    const double phi = C - (C - PIO2);
    const double plo = PIO2 - phi;

    for (int d = 0; d < HALF; ++d) {
        const float  e  = (float)d * (1.0f / 2048.0f);   // exact
        const double x  = (double)e * LOG2C;             // same rounding as ref
        const float  th = (float)cexp2(x);

        const double thd = (double)th;
        const long long mi = (long long)(thd * INVPIO2); // floor (positive)
        const double m = (double)mi;

        double t = thd - m * phi;    // m*phi exact; Sterbenz-exact subtraction
        t -= m * plo;                // m*plo exact; one rounding ~1e-16
        t -= m * PIO2LO;             // tiny correction

        T.e[d].theta = th;
        T.e[d].t_hi  = (float)t;
        T.e[d].t_lo  = (float)(t - (double)T.e[d].t_hi);
        T.e[d].m4    = (int)(mi & 3);
    }
    return T;
}

__device__ constexpr Table g_tab = make_table();

// ---------------- main kernel ----------------

__global__ __launch_bounds__(TPB, 4)
void rope_kernel(const float4* __restrict__ X, float4* __restrict__ O)
{
    const int d  = blockIdx.x * TPB + threadIdx.x;   // 0 .. HALF-1
    const int l0 = blockIdx.y * LPER;

    const float4 tab  = reinterpret_cast<const float4*>(g_tab.e)[d];
    const float theta = tab.x;
    const float t_hi  = tab.y;
    const float t_lo  = tab.z;
    const int   m4    = __float_as_int(tab.w);

    const size_t base0 = (size_t)l0 * D + d;         // float4 index

    // Phase 1: issue all 8 wide loads (deep MLP; hides DRAM latency)
    float4 x1[LPER], x2[LPER];
    #pragma unroll
    for (int j = 0; j < LPER; ++j) {
        const size_t base = base0 + (size_t)j * D;
        x1[j] = __ldcs(&X[base]);
        x2[j] = __ldcs(&X[base + HALF]);
    }

    // Phase 2: trig + rotate + store
    #pragma unroll
    for (int j = 0; j < LPER; ++j) {
        const int   pos_i = l0 + j + 1;
        const float pos   = (float)pos_i;                 // exact (<= 2^11)

        // Reference's angle: single-rounded fp32 product + exact residual.
        const float ang   = __fmul_rn(pos, theta);
        const float e_res = __fmaf_rn(pos, theta, -ang);  // exact: <=12-bit pos

        // u = pos * (theta mod pi/2) as float-float
        const float u_hi = __fmul_rn(pos, t_hi);
        const float u_lo = __fmaf_rn(pos, t_lo, __fmaf_rn(pos, t_hi, -u_hi));

        // First reduction: k <= 2048, 2-term fp32 Cody-Waite (err ~1e-7)
        const float kf = rintf(u_hi * 0.63661977f);
        float r = __fmaf_rn(-kf, 1.57079637f,    u_hi);
        r       = __fmaf_rn(-kf, -4.37113883e-8f, r);

        // Fold in product-rounding residual (|e_res| <= 1) and u_lo
        float rt = (r - e_res) + u_lo;

        // Second reduction: k2 in {-1,0,1}
        const float k2f = rintf(rt * 0.63661977f);
        rt = __fmaf_rn(-k2f, 1.57079637f,    rt);
        rt = __fmaf_rn(-k2f, -4.37113883e-8f, rt);

        const int q = ((pos_i & 3) * m4 + (int)kf + (int)k2f) & 3;

        // Polynomials on |rt| <~ pi/4
        const float t2 = rt * rt;
        float sp = fmaf(t2, 2.75573188e-6f, -1.98408351e-4f);
        sp = fmaf(sp, t2, 8.33333376e-3f);
        sp = fmaf(sp, t2, -1.66666672e-1f);
        sp = fmaf(sp * t2, rt, rt);
        float cp = fmaf(t2, -2.75573141e-7f, 2.47598227e-5f);
        cp = fmaf(cp, t2, -1.38888894e-3f);
        cp = fmaf(cp, t2, 4.16666679e-2f);
        cp = fmaf(cp, t2, -5.00000000e-1f);
        cp = fmaf(cp, t2, 1.0f);

        const float ss = (q & 1) ? cp : sp;
        const float cs = (q & 1) ? sp : cp;
        const float s  = (q & 2)       ? -ss : ss;
        const float c  = ((q + 1) & 2) ? -cs : cs;

        float4 o1, o2;
        o1.x = __fsub_rn(__fmul_rn(c, x1[j].x), __fmul_rn(s, x2[j].x));
        o1.y = __fsub_rn(__fmul_rn(c, x1[j].y), __fmul_rn(s, x2[j].y));
        o1.z = __fsub_rn(__fmul_rn(c, x1[j].z), __fmul_rn(s, x2[j].z));
        o1.w = __fsub_rn(__fmul_rn(c, x1[j].w), __fmul_rn(s, x2[j].w));

        o2.x = __fadd_rn(__fmul_rn(s, x1[j].x), __fmul_rn(c, x2[j].x));
        o2.y = __fadd_rn(__fmul_rn(s, x1[j].y), __fmul_rn(c, x2[j].y));
        o2.z = __fadd_rn(__fmul_rn(s, x1[j].z), __fmul_rn(c, x2[j].z));
        o2.w = __fadd_rn(__fmul_rn(s, x1[j].w), __fmul_rn(c, x2[j].w));

        const size_t base = base0 + (size_t)j * D;
        __stcs(&O[base],        o1);
        __stcs(&O[base + HALF], o2);
    }
}

extern "C" void kernel_launch(void* const* d_in, const int* in_sizes, int n_in,
                              void* d_out, int out_size)
{
    (void)in_sizes; (void)n_in; (void)out_size;
    const float4* X = (const float4*)d_in[0];
    float4*       O = (float4*)d_out;

    dim3 grid(HALF / TPB, L / LPER);            // (8, 512)
    rope_kernel<<<grid, TPB>>>(X, O);
}

// round 15
// speedup vs baseline: 1.0267x; 1.0267x over previous
#include <cuda_runtime.h>

// RoPE: X (L=2048, D=4096, N=4) fp32 -> out same shape.
// ang[l,d] = fl32((l+1) * theta_d), theta_d = 10000^(d/2048), angles to ~2e7.
//
// FINAL configuration (= R6). Five measurements of this exact binary:
// 43.78 / 45.82 / 44.67 / 43.74 / 44.26 us (mean 44.45, sigma ~0.85) ->
// session noise around the compulsory mixed-R/W HBM floor: 268 MB at
// ~6.0 TB/s in-kernel (kernel ~36us byte-stable) + ~8us fixed harness
// overhead. Optimization ledger (all bisected, measured):
//   fp64 hot path -> fp32 + constexpr table   (82 -> 48.7us)
//   batched MLP (loads before compute)        (DRAM 67.7 -> 73.5%)
//   occupancy 2 -> 4 CTAs/SM (LPER=4)         (-> 43.8us; occ 5 flat)
//   waves vs persistent/span/interleave       waves best (+1.4..5.5us others)
//   __stcs vs default vs __stwt stores        __stcs best
//   setup-kernel vs memcpy vs constexpr table constexpr best (-7us)

constexpr int L    = 2048;
constexpr int D    = 4096;   // feature dim in float4 units over N=4
constexpr int HALF = 2048;
constexpr int LPER = 4;
constexpr int TPB  = 256;

// ---------------- compile-time table generation ----------------

struct alignas(16) Entry { float theta, t_hi, t_lo; int m4; };
struct Table { Entry e[HALF]; };

// exp2(x), x in [0, 13.3), rel err ~5e-16 (compile-time IEEE doubles).
constexpr double cexp2(double x)
{
    const int    n = (int)(x + 0.5);
    const double f = x - (double)n;                  // [-0.5, 0.5], exact
    const double w = f * 0.69314718055994530942;     // f * ln2, |w| <= 0.347
    double p = 1.0;
    for (int k = 16; k >= 1; --k)                    // exp(w) Taylor, Horner
        p = 1.0 + p * w / (double)k;
    double s = 1.0;
    for (int i = 0; i < n; ++i) s *= 2.0;            // exact 2^n
    return s * p;                                    // exact scaling
}

constexpr Table make_table()
{
    Table T{};
    const double LOG2C   = 13.2877123795494493915;       // log2(10000)
    const double INVPIO2 = 0.63661977236758134308;       // 2/pi
    const double PIO2    = 1.57079632679489661923;       // double(pi/2)
    const double PIO2LO  = 6.12323399573676603587e-17;   // pi/2 - PIO2
    // Dekker split of PIO2: hi has <=26 bits -> m*hi exact for m < 2^24
    const double C   = 134217729.0 * PIO2;               // 2^27+1 splitter
    const double phi = C - (C - PIO2);
    const double plo = PIO2 - phi;

    for (int d = 0; d < HALF; ++d) {
        const float  e  = (float)d * (1.0f / 2048.0f);   // exact
        const double x  = (double)e * LOG2C;             // same rounding as ref
        const float  th = (float)cexp2(x);

        const double thd = (double)th;
        const long long mi = (long long)(thd * INVPIO2); // floor (positive)
        const double m = (double)mi;

        double t = thd - m * phi;    // m*phi exact; Sterbenz-exact subtraction
        t -= m * plo;                // m*plo exact; one rounding ~1e-16
        t -= m * PIO2LO;             // tiny correction

        T.e[d].theta = th;
        T.e[d].t_hi  = (float)t;
        T.e[d].t_lo  = (float)(t - (double)T.e[d].t_hi);
        T.e[d].m4    = (int)(mi & 3);
    }
    return T;
}

__device__ constexpr Table g_tab = make_table();

// ---------------- main kernel ----------------

__global__ __launch_bounds__(TPB, 4)
void rope_kernel(const float4* __restrict__ X, float4* __restrict__ O)
{
    const int d  = blockIdx.x * TPB + threadIdx.x;   // 0 .. HALF-1
    const int l0 = blockIdx.y * LPER;

    const float4 tab  = reinterpret_cast<const float4*>(g_tab.e)[d];
    const float theta = tab.x;
    const float t_hi  = tab.y;
    const float t_lo  = tab.z;
    const int   m4    = __float_as_int(tab.w);

    const size_t base0 = (size_t)l0 * D + d;         // float4 index

    // Phase 1: issue all 8 wide loads (deep MLP; hides DRAM latency)
    float4 x1[LPER], x2[LPER];
    #pragma unroll
    for (int j = 0; j < LPER; ++j) {
        const size_t base = base0 + (size_t)j * D;
        x1[j] = __ldcs(&X[base]);
        x2[j] = __ldcs(&X[base + HALF]);
    }

    // Phase 2: trig + rotate + store
    #pragma unroll
    for (int j = 0; j < LPER; ++j) {
        const int   pos_i = l0 + j + 1;
        const float pos   = (float)pos_i;                 // exact (<= 2^11)

        // Reference's angle: single-rounded fp32 product + exact residual.
        const float ang   = __fmul_rn(pos, theta);
        const float e_res = __fmaf_rn(pos, theta, -ang);  // exact: <=12-bit pos

        // u = pos * (theta mod pi/2) as float-float
        const float u_hi = __fmul_rn(pos, t_hi);
        const float u_lo = __fmaf_rn(pos, t_lo, __fmaf_rn(pos, t_hi, -u_hi));

        // First reduction: k <= 2048, 2-term fp32 Cody-Waite (err ~1e-7)
        const float kf = rintf(u_hi * 0.63661977f);
        float r = __fmaf_rn(-kf, 1.57079637f,    u_hi);
        r       = __fmaf_rn(-kf, -4.37113883e-8f, r);

        // Fold in product-rounding residual (|e_res| <= 1) and u_lo
        float rt = (r - e_res) + u_lo;

        // Second reduction: k2 in {-1,0,1}
        const float k2f = rintf(rt * 0.63661977f);
        rt = __fmaf_rn(-k2f, 1.57079637f,    rt);
        rt = __fmaf_rn(-k2f, -4.37113883e-8f, rt);

        const int q = ((pos_i & 3) * m4 + (int)kf + (int)k2f) & 3;

        // Polynomials on |rt| <~ pi/4
        const float t2 = rt * rt;
        float sp = fmaf(t2, 2.75573188e-6f, -1.98408351e-4f);
        sp = fmaf(sp, t2, 8.33333376e-3f);
        sp = fmaf(sp, t2, -1.66666672e-1f);
        sp = fmaf(sp * t2, rt, rt);
        float cp = fmaf(t2, -2.75573141e-7f, 2.47598227e-5f);
        cp = fmaf(cp, t2, -1.38888894e-3f);
        cp = fmaf(cp, t2, 4.16666679e-2f);
        cp = fmaf(cp, t2, -5.00000000e-1f);
        cp = fmaf(cp, t2, 1.0f);

        const float ss = (q & 1) ? cp : sp;
        const float cs = (q & 1) ? sp : cp;
        const float s  = (q & 2)       ? -ss : ss;
        const float c  = ((q + 1) & 2) ? -cs : cs;

        float4 o1, o2;
        o1.x = __fsub_rn(__fmul_rn(c, x1[j].x), __fmul_rn(s, x2[j].x));
        o1.y = __fsub_rn(__fmul_rn(c, x1[j].y), __fmul_rn(s, x2[j].y));
        o1.z = __fsub_rn(__fmul_rn(c, x1[j].z), __fmul_rn(s, x2[j].z));
        o1.w = __fsub_rn(__fmul_rn(c, x1[j].w), __fmul_rn(s, x2[j].w));

        o2.x = __fadd_rn(__fmul_rn(s, x1[j].x), __fmul_rn(c, x2[j].x));
        o2.y = __fadd_rn(__fmul_rn(s, x1[j].y), __fmul_rn(c, x2[j].y));
        o2.z = __fadd_rn(__fmul_rn(s, x1[j].z), __fmul_rn(c, x2[j].z));
        o2.w = __fadd_rn(__fmul_rn(s, x1[j].w), __fmul_rn(c, x2[j].w));

        const size_t base = base0 + (size_t)j * D;
        __stcs(&O[base],        o1);
        __stcs(&O[base + HALF], o2);
    }
}

extern "C" void kernel_launch(void* const* d_in, const int* in_sizes, int n_in,
                              void* d_out, int out_size)
{
    (void)in_sizes; (void)n_in; (void)out_size;
    const float4* X = (const float4*)d_in[0];
    float4*       O = (float4*)d_out;

    dim3 grid(HALF / TPB, L / LPER);            // (8, 512)
    rope_kernel<<<grid, TPB>>>(X, O);
}